// round 6
// baseline (speedup 1.0000x reference)
#include <cuda_runtime.h>
#include <cstdint>

#define L    768
#define D    256
#define NT   12
#define SPAN 8
#define NCTA 384

// ---------------- device scratch (static, no allocs) ----------------
__device__ __align__(16) float g_ht[8][L * D];        // ht per span-length diagonal
__device__ __align__(16) float g_BsL[1024 * 256];     // stacked interleaved [Wl|Gl], col'=4d+j
__device__ __align__(16) float g_BsR[1024 * 256];     // stacked interleaved [Wr|Gr]
__device__ __align__(16) float g_biasS[1024];         // stacked bias
__device__ __align__(16) float g_tagsc[8][L * NT];    // tag scores per diagonal (for gold)
__device__ __align__(16) float g_ex[L * NT * SPAN];   // exp(span scores) [i][t2][k]
__device__ __align__(16) float g_GT[11 * 96 * 96];    // chunk transfer matrices [c][j][o]
__device__ __align__(16) float g_sc[12 * 96];         // per-column log scales
__device__ __align__(16) float g_R[96 * 12];          // last chunk: A_767 rows [j][t2]
__device__ unsigned g_cnt;                            // grid barrier state (zero-init)
__device__ unsigned g_gen;

#define F2U(x) __float_as_uint(x)

__device__ __forceinline__ void mma_tf32(float& c0, float& c1, float& c2, float& c3,
                                         uint32_t a0, uint32_t a1, uint32_t a2, uint32_t a3,
                                         uint32_t b0, uint32_t b1)
{
    asm volatile("mma.sync.aligned.m16n8k8.row.col.f32.tf32.tf32.f32 "
                 "{%0,%1,%2,%3}, {%4,%5,%6,%7}, {%8,%9}, {%0,%1,%2,%3};\n"
                 : "+f"(c0), "+f"(c1), "+f"(c2), "+f"(c3)
                 : "r"(a0), "r"(a1), "r"(a2), "r"(a3), "r"(b0), "r"(b1));
}

__device__ __forceinline__ void cpa16(float* dst, const float* src)
{
    uint32_t d = (uint32_t)__cvta_generic_to_shared(dst);
    asm volatile("cp.async.cg.shared.global [%0], [%1], 16;\n" :: "r"(d), "l"(src));
}
#define CP_COMMIT() asm volatile("cp.async.commit_group;\n")
#define CP_WAIT(n)  asm volatile("cp.async.wait_group %0;\n" :: "n"(n))

// ---------------- software grid barrier (all NCTA co-resident by launch_bounds) ----
__device__ __forceinline__ void grid_bar()
{
    __syncthreads();
    if (threadIdx.x == 0) {
        __threadfence();
        unsigned gen = *(volatile unsigned*)&g_gen;
        if (atomicAdd(&g_cnt, 1u) == NCTA - 1u) {
            g_cnt = 0u;
            __threadfence();
            atomicAdd(&g_gen, 1u);
        } else {
            while (*(volatile unsigned*)&g_gen == gen) __nanosleep(64);
        }
        __threadfence();
    }
    __syncthreads();
}

#define POOL_FLOATS 9288

// ================== persistent mega kernel ==================
__global__ void __launch_bounds__(256, 3) mega_kernel(
    const float* __restrict__ feats, const float* __restrict__ Wd,
    const float* __restrict__ bd,
    const float* __restrict__ Wl, const float* __restrict__ Wr,
    const float* __restrict__ Gl, const float* __restrict__ Gr,
    const float* __restrict__ bl, const float* __restrict__ br,
    const float* __restrict__ bgl, const float* __restrict__ bgr,
    const float* __restrict__ Wt, const float* __restrict__ bt,
    const float* __restrict__ trans)
{
    __shared__ __align__(16) float pool[POOL_FLOATS];
    const int cta = blockIdx.x;
    const int tid = threadIdx.x;
    const int lane = tid & 31, warp = tid >> 5;
    const int g = lane >> 2, c = lane & 3;

    // ================= phase 0a: prep stacked weights + zero g_ex =================
    {
        int idx = cta * 256 + tid;
        if (idx < 65536) {
            int row = idx >> 6, k = (idx & 63) * 4;
            int d = row >> 2, j = row & 3;
            int srcrow = (j == 0) ? d : ((j - 1) * 256 + d);
            const float* sl4 = (j == 0) ? Wl : Gl;
            const float* sr4 = (j == 0) ? Wr : Gr;
            *(float4*)&g_BsL[(size_t)row * 256 + k] = *(const float4*)&sl4[(size_t)srcrow * 256 + k];
            *(float4*)&g_BsR[(size_t)row * 256 + k] = *(const float4*)&sr4[(size_t)srcrow * 256 + k];
        }
        if (idx < 1024) {
            int dd = idx >> 2, jj = idx & 3;
            g_biasS[idx] = (jj == 0) ? (bl[dd] + br[dd])
                                     : (bgl[(jj - 1) * 256 + dd] + bgr[(jj - 1) * 256 + dd]);
        }
        if (idx < L * NT * SPAN) g_ex[idx] = 0.f;
    }

    // ================= phase 0b: h = feats @ Wd^T + bd  (96 CTAs) =================
    if (cta < 96) {
        const int K = 512, NSTEP = 32;
        const int wm = warp & 3, wn = warp >> 2;
        const int m0 = (cta >> 3) * 64, n0 = (cta & 7) * 32;
        const int ar = tid >> 2, ac4 = (tid & 3) * 4;
        const int bi = tid & 127;
        const int brr = bi >> 2, bc4 = (bi & 3) * 4;
        const bool do_b = tid < 128;
        float acc[2][4] = {};

#pragma unroll
        for (int st = 0; st < 2; st++) {
            const int k0 = st * 16;
            cpa16(&pool[st * 1536 + ar * 24 + ac4], &feats[(size_t)(m0 + ar) * K + k0 + ac4]);
            if (do_b) cpa16(&pool[4608 + st * 768 + brr * 24 + bc4],
                            &Wd[(size_t)(n0 + brr) * K + k0 + bc4]);
            CP_COMMIT();
        }
        for (int step = 0; step < NSTEP; step++) {
            const int s = step % 3;
            if (step + 2 < NSTEP) {
                CP_WAIT(1);
                __syncthreads();
                const int k0 = (step + 2) * 16, s2 = (step + 2) % 3;
                cpa16(&pool[s2 * 1536 + ar * 24 + ac4], &feats[(size_t)(m0 + ar) * K + k0 + ac4]);
                if (do_b) cpa16(&pool[4608 + s2 * 768 + brr * 24 + bc4],
                                &Wd[(size_t)(n0 + brr) * K + k0 + bc4]);
                CP_COMMIT();
            } else {
                CP_WAIT(0);
                __syncthreads();
            }
#pragma unroll
            for (int kc = 0; kc < 2; kc++) {
                const int ko = kc * 8 + 2 * c;
                const float* p = &pool[s * 1536 + (wm * 16 + g) * 24 + ko];
                float2 fa0 = *(const float2*)p;
                float2 fa1 = *(const float2*)(p + 8 * 24);
#pragma unroll
                for (int ni = 0; ni < 2; ni++) {
                    const float* pb = &pool[4608 + s * 768 + (wn * 16 + ni * 8 + g) * 24 + ko];
                    float2 fb = *(const float2*)pb;
                    mma_tf32(acc[ni][0], acc[ni][1], acc[ni][2], acc[ni][3],
                             F2U(fa0.x), F2U(fa1.x), F2U(fa0.y), F2U(fa1.y),
                             F2U(fb.x), F2U(fb.y));
                }
            }
        }
#pragma unroll
        for (int ni = 0; ni < 2; ni++) {
            int col = n0 + wn * 16 + ni * 8 + 2 * c;
            float bv0 = bd[col], bv1 = bd[col + 1];
            int row0 = m0 + wm * 16 + g;
            g_ht[0][(size_t)row0 * 256 + col]           = acc[ni][0] + bv0;
            g_ht[0][(size_t)row0 * 256 + col + 1]       = acc[ni][1] + bv1;
            g_ht[0][(size_t)(row0 + 8) * 256 + col]     = acc[ni][2] + bv0;
            g_ht[0][(size_t)(row0 + 8) * 256 + col + 1] = acc[ni][3] + bv1;
        }
    }

    grid_bar();

    // ================= phase 1..7: fused dual GEMM + gate =================
    {
        const int wm = warp & 3, wn = warp >> 2;
        const int m0 = (cta >> 5) * 64, n0 = (cta & 31) * 32;
        const int ar = tid >> 2, ac4 = (tid & 3) * 4;
        const int bh = tid >> 7, bi = tid & 127;
        const int brr = bi >> 2, bc4 = (bi & 3) * 4;
        const float* bsrc = (bh ? g_BsR : g_BsL) + (size_t)n0 * 256;
        const int NSTEP = 16;

        for (int sl = 1; sl <= 7; sl++) {
            const int M = L - sl;
            const float* Aht = g_ht[sl - 1];
            float* htout = g_ht[sl];
            float acc[2][4] = {};

#pragma unroll
            for (int st = 0; st < 2; st++) {
                const int k0 = st * 16;
                cpa16(&pool[st * 1560 + ar * 24 + ac4], &Aht[(size_t)(m0 + ar) * 256 + k0 + ac4]);
                if (tid < 4) cpa16(&pool[st * 1560 + 64 * 24 + tid * 4],
                                   &Aht[(size_t)(m0 + 64) * 256 + k0 + tid * 4]);
                cpa16(&pool[4680 + st * 1536 + bh * 768 + brr * 24 + bc4],
                      &bsrc[(size_t)brr * 256 + k0 + bc4]);
                CP_COMMIT();
            }
            for (int step = 0; step < NSTEP; step++) {
                const int s = step % 3;
                if (step + 2 < NSTEP) {
                    CP_WAIT(1);
                    __syncthreads();
                    const int k0 = (step + 2) * 16, s2 = (step + 2) % 3;
                    cpa16(&pool[s2 * 1560 + ar * 24 + ac4],
                          &Aht[(size_t)(m0 + ar) * 256 + k0 + ac4]);
                    if (tid < 4) cpa16(&pool[s2 * 1560 + 64 * 24 + tid * 4],
                                       &Aht[(size_t)(m0 + 64) * 256 + k0 + tid * 4]);
                    cpa16(&pool[4680 + s2 * 1536 + bh * 768 + brr * 24 + bc4],
                          &bsrc[(size_t)brr * 256 + k0 + bc4]);
                    CP_COMMIT();
                } else {
                    CP_WAIT(0);
                    __syncthreads();
                }
#pragma unroll
                for (int kc = 0; kc < 2; kc++) {
                    const int ko = kc * 8 + 2 * c;
                    const float* p = &pool[s * 1560 + (wm * 16 + g) * 24 + ko];
                    float2 fa0 = *(const float2*)p;
                    float2 fa1 = *(const float2*)(p + 8 * 24);
                    float2 fr0 = *(const float2*)(p + 24);
                    float2 fr1 = *(const float2*)(p + 9 * 24);
#pragma unroll
                    for (int ni = 0; ni < 2; ni++) {
                        const int boff = (wn * 16 + ni * 8 + g) * 24 + ko;
                        float2 fbl = *(const float2*)&pool[4680 + s * 1536 + boff];
                        float2 fbr = *(const float2*)&pool[4680 + s * 1536 + 768 + boff];
                        mma_tf32(acc[ni][0], acc[ni][1], acc[ni][2], acc[ni][3],
                                 F2U(fa0.x), F2U(fa1.x), F2U(fa0.y), F2U(fa1.y),
                                 F2U(fbl.x), F2U(fbl.y));
                        mma_tf32(acc[ni][0], acc[ni][1], acc[ni][2], acc[ni][3],
                                 F2U(fr0.x), F2U(fr1.x), F2U(fr0.y), F2U(fr1.y),
                                 F2U(fbr.x), F2U(fbr.y));
                    }
                }
            }
#pragma unroll
            for (int ni = 0; ni < 2; ni++) {
                int colb = n0 + wn * 16 + ni * 8 + 2 * c;
                float b0 = g_biasS[colb], b1 = g_biasS[colb + 1];
                float z00 = acc[ni][0] + b0, z01 = acc[ni][1] + b1;
                float z10 = acc[ni][2] + b0, z11 = acc[ni][3] + b1;
                float w00 = __shfl_xor_sync(0xffffffffu, z00, 1);
                float w01 = __shfl_xor_sync(0xffffffffu, z01, 1);
                float w10 = __shfl_xor_sync(0xffffffffu, z10, 1);
                float w11 = __shfl_xor_sync(0xffffffffu, z11, 1);
                if ((c & 1) == 0) {
                    int d = colb >> 2;
                    int row0 = m0 + wm * 16 + g;
#pragma unroll
                    for (int rr = 0; rr < 2; rr++) {
                        int row = row0 + rr * 8;
                        if (row < M) {
                            float zh  = rr ? z10 : z00;
                            float zg0 = rr ? z11 : z01;
                            float zg1 = rr ? w10 : w00;
                            float zg2 = rr ? w11 : w01;
                            float lft = Aht[(size_t)row * 256 + d];
                            float rgt = Aht[(size_t)(row + 1) * 256 + d];
                            float hh = 4.f / (1.f + __expf(-zh)) - 2.f;
                            float mx = fmaxf(zg0, fmaxf(zg1, zg2));
                            float e0 = __expf(zg0 - mx), e1 = __expf(zg1 - mx),
                                  e2 = __expf(zg2 - mx);
                            float inv = 1.f / (e0 + e1 + e2);
                            htout[(size_t)row * 256 + d] =
                                (e0 * hh + e1 * lft + e2 * rgt) * inv;
                        }
                    }
                }
            }
            grid_bar();
        }
    }

    // ================= phase 8: tag scores + exp gather =================
    {
        for (int i = tid; i < NT * D; i += 256) pool[i] = Wt[i];
        __syncthreads();
#pragma unroll
        for (int rep = 0; rep < 2; rep++) {
            int gw = cta * 8 + warp + rep * 3072;
            int sl = gw / L;
            int pos = gw - sl * L;
            if (pos + sl < L) {
                const float* hp = g_ht[sl] + (size_t)pos * D;
                float4 h0 = *(const float4*)&hp[lane * 8];
                float4 h1 = *(const float4*)&hp[lane * 8 + 4];
                float hv[8] = {h0.x,h0.y,h0.z,h0.w,h1.x,h1.y,h1.z,h1.w};
                int i_end = pos + sl, kk = 7 - sl;
#pragma unroll
                for (int t = 0; t < NT; t++) {
                    const float* wp = &pool[t * D + lane * 8];
                    float4 w0 = *(const float4*)wp;
                    float4 w1 = *(const float4*)(wp + 4);
                    float s = hv[0]*w0.x + hv[1]*w0.y + hv[2]*w0.z + hv[3]*w0.w
                            + hv[4]*w1.x + hv[5]*w1.y + hv[6]*w1.z + hv[7]*w1.w;
#pragma unroll
                    for (int o = 16; o; o >>= 1) s += __shfl_xor_sync(0xffffffffu, s, o);
                    if (lane == 0) {
                        float val = s + bt[t];
                        g_tagsc[sl][pos * NT + t] = val;
                        g_ex[((size_t)i_end * NT + t) * SPAN + kk] = __expf(val);
                    }
                }
            }
        }
    }

    grid_bar();

    // ================= phase 9: chunk transfer matrices (basis runs) =================
    // 12 chunks x 96 basis columns = 1152 runs; 3 per CTA (warps 0..2).
    if (warp < 3) {
        const int run = cta * 3 + warp;            // 0..1151
        const int chunk = run / 96, j = run - chunk * 96;
        const int slotj = j / 12, tj = j - slotj * 12;
        const int t2 = (lane < 12) ? lane : 11;

        float eTc[12];
#pragma unroll
        for (int t1 = 0; t1 < 12; t1++) eTc[t1] = __expf(trans[t1 * 12 + t2]);

        float Cw[8];
#pragma unroll
        for (int k = 0; k < 8; k++) Cw[k] = 0.f;
        if (lane == tj) Cw[slotj] = 1.f;
        float sc = 0.f;
        float lastA = 0.f;

        const float4* exb = (const float4*)(g_ex + ((size_t)(chunk * 64) * 12 + t2) * 8);
        float4 c0 = exb[0], c1 = exb[1];
        float4 n0 = exb[24], n1 = exb[25];

        for (int blk = 0; blk < 8; blk++) {
#pragma unroll
            for (int u = 0; u < 8; u++) {
                const int li = blk * 8 + u;
                float4 f0 = c0, f1 = c1;
                c0 = n0; c1 = n1;
                if (li + 2 < 64) {
                    n0 = exb[(li + 2) * 24];
                    n1 = exb[(li + 2) * 24 + 1];
                }
                float e0=f0.x,e1=f0.y,e2=f0.z,e3=f0.w,e4=f1.x,e5=f1.y,e6=f1.z,e7=f1.w;
                float v01 = fmaf(e1, Cw[(u + 1) & 7], e0 * Cw[(u + 0) & 7]);
                float v23 = fmaf(e3, Cw[(u + 3) & 7], e2 * Cw[(u + 2) & 7]);
                float v45 = fmaf(e5, Cw[(u + 5) & 7], e4 * Cw[(u + 4) & 7]);
                float v6  = e6 * Cw[(u + 6) & 7];
                float A = fmaf(e7, Cw[(u + 7) & 7], (v01 + v23) + (v45 + v6));
                lastA = A;
                float bnA = 0.f, bnB = 0.f;
#pragma unroll
                for (int t1 = 0; t1 < 6; t1++) {
                    bnA = fmaf(eTc[t1],     __shfl_sync(0xffffffffu, A, t1),     bnA);
                    bnB = fmaf(eTc[t1 + 6], __shfl_sync(0xffffffffu, A, t1 + 6), bnB);
                }
                Cw[u] = bnA + bnB;
            }
            if (blk != 7) {                         // rescale window (all slots, same scale)
                float m = (lane < 12) ? Cw[7] : 0.f;
#pragma unroll
                for (int o = 16; o; o >>= 1) m = fmaxf(m, __shfl_xor_sync(0xffffffffu, m, o));
                if (m < 1e-30f) m = 1.f;
                float inv = 1.f / m;
#pragma unroll
                for (int k = 0; k < 8; k++) Cw[k] *= inv;
                sc += __logf(m);
            }
        }

        if (chunk < 11) {
            if (lane < 12) {
#pragma unroll
                for (int slot = 0; slot < 8; slot++)
                    g_GT[((size_t)chunk * 96 + j) * 96 + slot * 12 + lane] = Cw[slot];
            }
            if (lane == 0) g_sc[chunk * 96 + j] = sc;
        } else {
            if (lane < 12) g_R[j * 12 + lane] = lastA;
            if (lane == 0) g_sc[11 * 96 + j] = sc;
        }
    }
}

// ---------------- phase B: gold + sequential chunk matvecs (1 CTA) ----------------
__global__ void forward2(const float* __restrict__ trans,
                         const float* __restrict__ bt,
                         const int* __restrict__ tags,
                         float* __restrict__ out)
{
    __shared__ float s_sh[96], st_sh[96], sc_sh[96], lv[11];
    __shared__ float gold_sh;
    const int tid = threadIdx.x;                   // 128 threads

    if (tid < 32) {
        float gold = 0.f;
        for (int s = tid; s < 96; s += 32) {
            int i  = tags[s * 4 + 0];
            int j  = tags[s * 4 + 1];
            int pr = tags[s * 4 + 2];
            int t  = tags[s * 4 + 3];
            int sl = j - i;
            float base = (sl >= 0 && sl < SPAN && i >= 0 && i + sl < L)
                       ? g_tagsc[sl][i * NT + t] : bt[t];
            gold += base + trans[pr * NT + t];
        }
#pragma unroll
        for (int o = 16; o; o >>= 1) gold += __shfl_xor_sync(0xffffffffu, gold, o);
        if (tid == 0) gold_sh = gold;
    }
    // initial window: C_{-1}[t] = exp(trans[START=10][t]) in slot 7; rest 0
    if (tid < 96) s_sh[tid] = (tid >= 84) ? expf(trans[10 * 12 + (tid - 84)]) : 0.f;
    __syncthreads();

    float Sacc = 0.f;
    for (int cch = 0; cch < 11; cch++) {
        if (tid < 96) sc_sh[tid] = g_sc[cch * 96 + tid];
        __syncthreads();
        float mc = -1e30f;
        for (int j = 0; j < 96; j++) mc = fmaxf(mc, sc_sh[j]);
        if (tid < 96) st_sh[tid] = s_sh[tid] * expf(sc_sh[tid] - mc);
        __syncthreads();
        float snew = 0.f;
        if (tid < 96) {
            const float* G = g_GT + (size_t)cch * 96 * 96 + tid;
            float a0 = 0.f, a1 = 0.f, a2 = 0.f, a3 = 0.f;
#pragma unroll 4
            for (int j = 0; j < 96; j += 4) {
                a0 = fmaf(G[(j + 0) * 96], st_sh[j + 0], a0);
                a1 = fmaf(G[(j + 1) * 96], st_sh[j + 1], a1);
                a2 = fmaf(G[(j + 2) * 96], st_sh[j + 2], a2);
                a3 = fmaf(G[(j + 3) * 96], st_sh[j + 3], a3);
            }
            snew = (a0 + a1) + (a2 + a3);
        }
        __syncthreads();
        if (tid < 96) s_sh[tid] = snew;
        __syncthreads();
        float mx = 0.f;
        for (int j = 0; j < 96; j++) mx = fmaxf(mx, s_sh[j]);
        __syncthreads();
        if (tid < 96) s_sh[tid] = snew / mx;
        Sacc += mc + logf(mx);
        __syncthreads();
    }

    // final chunk 11: per-tag dots, logZ = 11*(S+mc) + sum log
    if (tid < 96) sc_sh[tid] = g_sc[11 * 96 + tid];
    __syncthreads();
    float mc = -1e30f;
    for (int j = 0; j < 96; j++) mc = fmaxf(mc, sc_sh[j]);
    if (tid < 96) st_sh[tid] = s_sh[tid] * expf(sc_sh[tid] - mc);
    __syncthreads();
    if (tid < 11) {
        float a0 = 0.f, a1 = 0.f, a2 = 0.f, a3 = 0.f;
        for (int j = 0; j < 96; j += 4) {
            a0 = fmaf(g_R[(j + 0) * 12 + tid], st_sh[j + 0], a0);
            a1 = fmaf(g_R[(j + 1) * 12 + tid], st_sh[j + 1], a1);
            a2 = fmaf(g_R[(j + 2) * 12 + tid], st_sh[j + 2], a2);
            a3 = fmaf(g_R[(j + 3) * 12 + tid], st_sh[j + 3], a3);
        }
        lv[tid] = logf((a0 + a1) + (a2 + a3));
    }
    __syncthreads();
    if (tid == 0) {
        float logZ = 11.f * (Sacc + mc);
        for (int t = 0; t < 11; t++) logZ += lv[t];
        out[0] = logZ - gold_sh;
    }
}

// ---------------- launch ----------------
extern "C" void kernel_launch(void* const* d_in, const int* in_sizes, int n_in,
                              void* d_out, int out_size)
{
    const float* feats = (const float*)d_in[0];
    const int*   tags  = (const int*)d_in[1];
    const float* Wd    = (const float*)d_in[2];
    const float* bd    = (const float*)d_in[3];
    const float* Wl    = (const float*)d_in[4];
    const float* bl    = (const float*)d_in[5];
    const float* Wr    = (const float*)d_in[6];
    const float* br    = (const float*)d_in[7];
    const float* Gl    = (const float*)d_in[8];
    const float* bgl   = (const float*)d_in[9];
    const float* Gr    = (const float*)d_in[10];
    const float* bgr   = (const float*)d_in[11];
    const float* Wt    = (const float*)d_in[12];
    const float* bt    = (const float*)d_in[13];
    const float* trans = (const float*)d_in[14];
    float* out = (float*)d_out;

    mega_kernel<<<NCTA, 256>>>(feats, Wd, bd, Wl, Wr, Gl, Gr,
                               bl, br, bgl, bgr, Wt, bt, trans);
    forward2<<<1, 128>>>(trans, bt, tags, out);
}

// round 7
// speedup vs baseline: 1.2276x; 1.2276x over previous
#include <cuda_runtime.h>
#include <cstdint>

#define L    768
#define D    256
#define NT   12
#define SPAN 8
#define NCTA 384

// ---------------- device scratch (static, no allocs) ----------------
__device__ __align__(16) float g_ht[8][L * D];        // ht per span-length diagonal
__device__ __align__(16) float g_BsL[1024 * 256];     // stacked interleaved [Wl|Gl], col'=4d+j
__device__ __align__(16) float g_BsR[1024 * 256];     // stacked interleaved [Wr|Gr]
__device__ __align__(16) float g_biasS[1024];         // stacked bias
__device__ __align__(16) float g_tagsc[8][L * NT];    // tag scores per diagonal (for gold)
__device__ __align__(16) float g_ex[L * NT * SPAN];   // exp(span scores) [i][t2][k]
__device__ __align__(16) float g_GT[11 * 96 * 96];    // chunk transfer matrices [c][j][o]
__device__ __align__(16) float g_sc[12 * 96];         // per-column log scales
__device__ __align__(16) float g_R[96 * 12];          // last chunk: A_767 rows [j][t2]
__device__ unsigned g_cnt;                            // grid barrier state (zero-init)
__device__ unsigned g_gen;

#define F2U(x) __float_as_uint(x)

__device__ __forceinline__ void mma_tf32(float& c0, float& c1, float& c2, float& c3,
                                         uint32_t a0, uint32_t a1, uint32_t a2, uint32_t a3,
                                         uint32_t b0, uint32_t b1)
{
    asm volatile("mma.sync.aligned.m16n8k8.row.col.f32.tf32.tf32.f32 "
                 "{%0,%1,%2,%3}, {%4,%5,%6,%7}, {%8,%9}, {%0,%1,%2,%3};\n"
                 : "+f"(c0), "+f"(c1), "+f"(c2), "+f"(c3)
                 : "r"(a0), "r"(a1), "r"(a2), "r"(a3), "r"(b0), "r"(b1));
}

__device__ __forceinline__ void cpa16(float* dst, const float* src)
{
    uint32_t d = (uint32_t)__cvta_generic_to_shared(dst);
    asm volatile("cp.async.cg.shared.global [%0], [%1], 16;\n" :: "r"(d), "l"(src));
}
#define CP_COMMIT() asm volatile("cp.async.commit_group;\n")
#define CP_WAIT(n)  asm volatile("cp.async.wait_group %0;\n" :: "n"(n))

// ---------------- software grid barrier (all NCTA co-resident by launch_bounds) ----
__device__ __forceinline__ void grid_bar()
{
    __syncthreads();
    if (threadIdx.x == 0) {
        __threadfence();
        unsigned gen = *(volatile unsigned*)&g_gen;
        if (atomicAdd(&g_cnt, 1u) == NCTA - 1u) {
            g_cnt = 0u;
            __threadfence();
            atomicAdd(&g_gen, 1u);
        } else {
            while (*(volatile unsigned*)&g_gen == gen) __nanosleep(64);
        }
        __threadfence();
    }
    __syncthreads();
}

#define POOL_FLOATS 9288

// ================== persistent mega kernel (unchanged from R6) ==================
__global__ void __launch_bounds__(256, 3) mega_kernel(
    const float* __restrict__ feats, const float* __restrict__ Wd,
    const float* __restrict__ bd,
    const float* __restrict__ Wl, const float* __restrict__ Wr,
    const float* __restrict__ Gl, const float* __restrict__ Gr,
    const float* __restrict__ bl, const float* __restrict__ br,
    const float* __restrict__ bgl, const float* __restrict__ bgr,
    const float* __restrict__ Wt, const float* __restrict__ bt,
    const float* __restrict__ trans)
{
    __shared__ __align__(16) float pool[POOL_FLOATS];
    const int cta = blockIdx.x;
    const int tid = threadIdx.x;
    const int lane = tid & 31, warp = tid >> 5;
    const int g = lane >> 2, c = lane & 3;

    // ================= phase 0a: prep stacked weights + zero g_ex =================
    {
        int idx = cta * 256 + tid;
        if (idx < 65536) {
            int row = idx >> 6, k = (idx & 63) * 4;
            int d = row >> 2, j = row & 3;
            int srcrow = (j == 0) ? d : ((j - 1) * 256 + d);
            const float* sl4 = (j == 0) ? Wl : Gl;
            const float* sr4 = (j == 0) ? Wr : Gr;
            *(float4*)&g_BsL[(size_t)row * 256 + k] = *(const float4*)&sl4[(size_t)srcrow * 256 + k];
            *(float4*)&g_BsR[(size_t)row * 256 + k] = *(const float4*)&sr4[(size_t)srcrow * 256 + k];
        }
        if (idx < 1024) {
            int dd = idx >> 2, jj = idx & 3;
            g_biasS[idx] = (jj == 0) ? (bl[dd] + br[dd])
                                     : (bgl[(jj - 1) * 256 + dd] + bgr[(jj - 1) * 256 + dd]);
        }
        if (idx < L * NT * SPAN) g_ex[idx] = 0.f;
    }

    // ================= phase 0b: h = feats @ Wd^T + bd  (96 CTAs) =================
    if (cta < 96) {
        const int K = 512, NSTEP = 32;
        const int wm = warp & 3, wn = warp >> 2;
        const int m0 = (cta >> 3) * 64, n0 = (cta & 7) * 32;
        const int ar = tid >> 2, ac4 = (tid & 3) * 4;
        const int bi = tid & 127;
        const int brr = bi >> 2, bc4 = (bi & 3) * 4;
        const bool do_b = tid < 128;
        float acc[2][4] = {};

#pragma unroll
        for (int st = 0; st < 2; st++) {
            const int k0 = st * 16;
            cpa16(&pool[st * 1536 + ar * 24 + ac4], &feats[(size_t)(m0 + ar) * K + k0 + ac4]);
            if (do_b) cpa16(&pool[4608 + st * 768 + brr * 24 + bc4],
                            &Wd[(size_t)(n0 + brr) * K + k0 + bc4]);
            CP_COMMIT();
        }
        for (int step = 0; step < NSTEP; step++) {
            const int s = step % 3;
            if (step + 2 < NSTEP) {
                CP_WAIT(1);
                __syncthreads();
                const int k0 = (step + 2) * 16, s2 = (step + 2) % 3;
                cpa16(&pool[s2 * 1536 + ar * 24 + ac4], &feats[(size_t)(m0 + ar) * K + k0 + ac4]);
                if (do_b) cpa16(&pool[4608 + s2 * 768 + brr * 24 + bc4],
                                &Wd[(size_t)(n0 + brr) * K + k0 + bc4]);
                CP_COMMIT();
            } else {
                CP_WAIT(0);
                __syncthreads();
            }
#pragma unroll
            for (int kc = 0; kc < 2; kc++) {
                const int ko = kc * 8 + 2 * c;
                const float* p = &pool[s * 1536 + (wm * 16 + g) * 24 + ko];
                float2 fa0 = *(const float2*)p;
                float2 fa1 = *(const float2*)(p + 8 * 24);
#pragma unroll
                for (int ni = 0; ni < 2; ni++) {
                    const float* pb = &pool[4608 + s * 768 + (wn * 16 + ni * 8 + g) * 24 + ko];
                    float2 fb = *(const float2*)pb;
                    mma_tf32(acc[ni][0], acc[ni][1], acc[ni][2], acc[ni][3],
                             F2U(fa0.x), F2U(fa1.x), F2U(fa0.y), F2U(fa1.y),
                             F2U(fb.x), F2U(fb.y));
                }
            }
        }
#pragma unroll
        for (int ni = 0; ni < 2; ni++) {
            int col = n0 + wn * 16 + ni * 8 + 2 * c;
            float bv0 = bd[col], bv1 = bd[col + 1];
            int row0 = m0 + wm * 16 + g;
            g_ht[0][(size_t)row0 * 256 + col]           = acc[ni][0] + bv0;
            g_ht[0][(size_t)row0 * 256 + col + 1]       = acc[ni][1] + bv1;
            g_ht[0][(size_t)(row0 + 8) * 256 + col]     = acc[ni][2] + bv0;
            g_ht[0][(size_t)(row0 + 8) * 256 + col + 1] = acc[ni][3] + bv1;
        }
    }

    grid_bar();

    // ================= phase 1..7: fused dual GEMM + gate =================
    {
        const int wm = warp & 3, wn = warp >> 2;
        const int m0 = (cta >> 5) * 64, n0 = (cta & 31) * 32;
        const int ar = tid >> 2, ac4 = (tid & 3) * 4;
        const int bh = tid >> 7, bi = tid & 127;
        const int brr = bi >> 2, bc4 = (bi & 3) * 4;
        const float* bsrc = (bh ? g_BsR : g_BsL) + (size_t)n0 * 256;
        const int NSTEP = 16;

        for (int sl = 1; sl <= 7; sl++) {
            const int M = L - sl;
            const float* Aht = g_ht[sl - 1];
            float* htout = g_ht[sl];
            float acc[2][4] = {};

#pragma unroll
            for (int st = 0; st < 2; st++) {
                const int k0 = st * 16;
                cpa16(&pool[st * 1560 + ar * 24 + ac4], &Aht[(size_t)(m0 + ar) * 256 + k0 + ac4]);
                if (tid < 4) cpa16(&pool[st * 1560 + 64 * 24 + tid * 4],
                                   &Aht[(size_t)(m0 + 64) * 256 + k0 + tid * 4]);
                cpa16(&pool[4680 + st * 1536 + bh * 768 + brr * 24 + bc4],
                      &bsrc[(size_t)brr * 256 + k0 + bc4]);
                CP_COMMIT();
            }
            for (int step = 0; step < NSTEP; step++) {
                const int s = step % 3;
                if (step + 2 < NSTEP) {
                    CP_WAIT(1);
                    __syncthreads();
                    const int k0 = (step + 2) * 16, s2 = (step + 2) % 3;
                    cpa16(&pool[s2 * 1560 + ar * 24 + ac4],
                          &Aht[(size_t)(m0 + ar) * 256 + k0 + ac4]);
                    if (tid < 4) cpa16(&pool[s2 * 1560 + 64 * 24 + tid * 4],
                                       &Aht[(size_t)(m0 + 64) * 256 + k0 + tid * 4]);
                    cpa16(&pool[4680 + s2 * 1536 + bh * 768 + brr * 24 + bc4],
                          &bsrc[(size_t)brr * 256 + k0 + bc4]);
                    CP_COMMIT();
                } else {
                    CP_WAIT(0);
                    __syncthreads();
                }
#pragma unroll
                for (int kc = 0; kc < 2; kc++) {
                    const int ko = kc * 8 + 2 * c;
                    const float* p = &pool[s * 1560 + (wm * 16 + g) * 24 + ko];
                    float2 fa0 = *(const float2*)p;
                    float2 fa1 = *(const float2*)(p + 8 * 24);
                    float2 fr0 = *(const float2*)(p + 24);
                    float2 fr1 = *(const float2*)(p + 9 * 24);
#pragma unroll
                    for (int ni = 0; ni < 2; ni++) {
                        const int boff = (wn * 16 + ni * 8 + g) * 24 + ko;
                        float2 fbl = *(const float2*)&pool[4680 + s * 1536 + boff];
                        float2 fbr = *(const float2*)&pool[4680 + s * 1536 + 768 + boff];
                        mma_tf32(acc[ni][0], acc[ni][1], acc[ni][2], acc[ni][3],
                                 F2U(fa0.x), F2U(fa1.x), F2U(fa0.y), F2U(fa1.y),
                                 F2U(fbl.x), F2U(fbl.y));
                        mma_tf32(acc[ni][0], acc[ni][1], acc[ni][2], acc[ni][3],
                                 F2U(fr0.x), F2U(fr1.x), F2U(fr0.y), F2U(fr1.y),
                                 F2U(fbr.x), F2U(fbr.y));
                    }
                }
            }
#pragma unroll
            for (int ni = 0; ni < 2; ni++) {
                int colb = n0 + wn * 16 + ni * 8 + 2 * c;
                float b0 = g_biasS[colb], b1 = g_biasS[colb + 1];
                float z00 = acc[ni][0] + b0, z01 = acc[ni][1] + b1;
                float z10 = acc[ni][2] + b0, z11 = acc[ni][3] + b1;
                float w00 = __shfl_xor_sync(0xffffffffu, z00, 1);
                float w01 = __shfl_xor_sync(0xffffffffu, z01, 1);
                float w10 = __shfl_xor_sync(0xffffffffu, z10, 1);
                float w11 = __shfl_xor_sync(0xffffffffu, z11, 1);
                if ((c & 1) == 0) {
                    int d = colb >> 2;
                    int row0 = m0 + wm * 16 + g;
#pragma unroll
                    for (int rr = 0; rr < 2; rr++) {
                        int row = row0 + rr * 8;
                        if (row < M) {
                            float zh  = rr ? z10 : z00;
                            float zg0 = rr ? z11 : z01;
                            float zg1 = rr ? w10 : w00;
                            float zg2 = rr ? w11 : w01;
                            float lft = Aht[(size_t)row * 256 + d];
                            float rgt = Aht[(size_t)(row + 1) * 256 + d];
                            float hh = 4.f / (1.f + __expf(-zh)) - 2.f;
                            float mx = fmaxf(zg0, fmaxf(zg1, zg2));
                            float e0 = __expf(zg0 - mx), e1 = __expf(zg1 - mx),
                                  e2 = __expf(zg2 - mx);
                            float inv = 1.f / (e0 + e1 + e2);
                            htout[(size_t)row * 256 + d] =
                                (e0 * hh + e1 * lft + e2 * rgt) * inv;
                        }
                    }
                }
            }
            grid_bar();
        }
    }

    // ================= phase 8: tag scores + exp gather =================
    {
        for (int i = tid; i < NT * D; i += 256) pool[i] = Wt[i];
        __syncthreads();
#pragma unroll
        for (int rep = 0; rep < 2; rep++) {
            int gw = cta * 8 + warp + rep * 3072;
            int sl = gw / L;
            int pos = gw - sl * L;
            if (pos + sl < L) {
                const float* hp = g_ht[sl] + (size_t)pos * D;
                float4 h0 = *(const float4*)&hp[lane * 8];
                float4 h1 = *(const float4*)&hp[lane * 8 + 4];
                float hv[8] = {h0.x,h0.y,h0.z,h0.w,h1.x,h1.y,h1.z,h1.w};
                int i_end = pos + sl, kk = 7 - sl;
#pragma unroll
                for (int t = 0; t < NT; t++) {
                    const float* wp = &pool[t * D + lane * 8];
                    float4 w0 = *(const float4*)wp;
                    float4 w1 = *(const float4*)(wp + 4);
                    float s = hv[0]*w0.x + hv[1]*w0.y + hv[2]*w0.z + hv[3]*w0.w
                            + hv[4]*w1.x + hv[5]*w1.y + hv[6]*w1.z + hv[7]*w1.w;
#pragma unroll
                    for (int o = 16; o; o >>= 1) s += __shfl_xor_sync(0xffffffffu, s, o);
                    if (lane == 0) {
                        float val = s + bt[t];
                        g_tagsc[sl][pos * NT + t] = val;
                        g_ex[((size_t)i_end * NT + t) * SPAN + kk] = __expf(val);
                    }
                }
            }
        }
    }

    grid_bar();

    // ================= phase 9: chunk transfer matrices (basis runs) =================
    if (warp < 3) {
        const int run = cta * 3 + warp;            // 0..1151
        const int chunk = run / 96, j = run - chunk * 96;
        const int slotj = j / 12, tj = j - slotj * 12;
        const int t2 = (lane < 12) ? lane : 11;

        float eTc[12];
#pragma unroll
        for (int t1 = 0; t1 < 12; t1++) eTc[t1] = __expf(trans[t1 * 12 + t2]);

        float Cw[8];
#pragma unroll
        for (int k = 0; k < 8; k++) Cw[k] = 0.f;
        if (lane == tj) Cw[slotj] = 1.f;
        float sc = 0.f;
        float lastA = 0.f;

        const float4* exb = (const float4*)(g_ex + ((size_t)(chunk * 64) * 12 + t2) * 8);
        float4 c0 = exb[0], c1 = exb[1];
        float4 n0 = exb[24], n1 = exb[25];

        for (int blk = 0; blk < 8; blk++) {
#pragma unroll
            for (int u = 0; u < 8; u++) {
                const int li = blk * 8 + u;
                float4 f0 = c0, f1 = c1;
                c0 = n0; c1 = n1;
                if (li + 2 < 64) {
                    n0 = exb[(li + 2) * 24];
                    n1 = exb[(li + 2) * 24 + 1];
                }
                float e0=f0.x,e1=f0.y,e2=f0.z,e3=f0.w,e4=f1.x,e5=f1.y,e6=f1.z,e7=f1.w;
                float v01 = fmaf(e1, Cw[(u + 1) & 7], e0 * Cw[(u + 0) & 7]);
                float v23 = fmaf(e3, Cw[(u + 3) & 7], e2 * Cw[(u + 2) & 7]);
                float v45 = fmaf(e5, Cw[(u + 5) & 7], e4 * Cw[(u + 4) & 7]);
                float v6  = e6 * Cw[(u + 6) & 7];
                float A = fmaf(e7, Cw[(u + 7) & 7], (v01 + v23) + (v45 + v6));
                lastA = A;
                float bnA = 0.f, bnB = 0.f;
#pragma unroll
                for (int t1 = 0; t1 < 6; t1++) {
                    bnA = fmaf(eTc[t1],     __shfl_sync(0xffffffffu, A, t1),     bnA);
                    bnB = fmaf(eTc[t1 + 6], __shfl_sync(0xffffffffu, A, t1 + 6), bnB);
                }
                Cw[u] = bnA + bnB;
            }
            if (blk != 7) {
                float m = (lane < 12) ? Cw[7] : 0.f;
#pragma unroll
                for (int o = 16; o; o >>= 1) m = fmaxf(m, __shfl_xor_sync(0xffffffffu, m, o));
                if (m < 1e-30f) m = 1.f;
                float inv = 1.f / m;
#pragma unroll
                for (int k = 0; k < 8; k++) Cw[k] *= inv;
                sc += __logf(m);
            }
        }

        if (chunk < 11) {
            if (lane < 12) {
#pragma unroll
                for (int slot = 0; slot < 8; slot++)
                    g_GT[((size_t)chunk * 96 + j) * 96 + slot * 12 + lane] = Cw[slot];
            }
            if (lane == 0) g_sc[chunk * 96 + j] = sc;
        } else {
            if (lane < 12) g_R[j * 12 + lane] = lastA;
            if (lane == 0) g_sc[11 * 96 + j] = sc;
        }
    }
}

// ---------------- phase B v2: 768 threads, high-MLP matvec chain ----------------
__global__ void __launch_bounds__(768) forward2(const float* __restrict__ trans,
                                                const float* __restrict__ bt,
                                                const int* __restrict__ tags,
                                                float* __restrict__ out)
{
    __shared__ float s_sh[96], st_sh[96], scall[1152], Rsh[1152], part[768];
    __shared__ float wred[3], wred2[3], lv[11];
    __shared__ float gold_sh;
    const int tid = threadIdx.x;                   // 768 threads
    const int p = tid / 96, o = tid - p * 96;      // p<8, o<96

    // stage per-column scales + last-chunk rows into shared (coalesced)
    for (int i = tid; i < 1152; i += 768) { scall[i] = g_sc[i]; Rsh[i] = g_R[i]; }

    // gold score (warp 0)
    if (tid < 32) {
        float gold = 0.f;
        for (int s = tid; s < 96; s += 32) {
            int i  = tags[s * 4 + 0];
            int j  = tags[s * 4 + 1];
            int pr = tags[s * 4 + 2];
            int t  = tags[s * 4 + 3];
            int sl = j - i;
            float base = (sl >= 0 && sl < SPAN && i >= 0 && i + sl < L)
                       ? g_tagsc[sl][i * NT + t] : bt[t];
            gold += base + trans[pr * NT + t];
        }
#pragma unroll
        for (int off = 16; off; off >>= 1) gold += __shfl_xor_sync(0xffffffffu, gold, off);
        if (tid == 0) gold_sh = gold;
    }
    // initial window: C_{-1}[t] = exp(trans[START=10][t]) in slot 7
    if (tid < 96) s_sh[tid] = (tid >= 84) ? expf(trans[10 * 12 + (tid - 84)]) : 0.f;
    __syncthreads();

    float Sacc = 0.f;
    float mc = 0.f;
    for (int cch = 0; cch < 12; cch++) {
        // mc = max_j scall[cch][j]   (shfl + 3-word combine)
        float m = (tid < 96) ? scall[cch * 96 + tid] : -3e38f;
#pragma unroll
        for (int off = 16; off; off >>= 1) m = fmaxf(m, __shfl_xor_sync(0xffffffffu, m, off));
        if (tid < 96 && (tid & 31) == 0) wred[tid >> 5] = m;
        __syncthreads();                                             // sync1
        mc = fmaxf(fmaxf(wred[0], wred[1]), wred[2]);
        if (tid < 96) st_sh[tid] = s_sh[tid] * expf(scall[cch * 96 + tid] - mc);
        __syncthreads();                                             // sync2

        if (cch < 11) {
            // matvec: thread (p,o) accumulates 12 terms, coalesced LDG from L2
            const float* G = g_GT + (size_t)cch * 9216 + (size_t)(p * 12) * 96 + o;
            const float* sv = &st_sh[p * 12];
            float a0 = 0.f, a1 = 0.f, a2 = 0.f, a3 = 0.f;
#pragma unroll
            for (int j = 0; j < 12; j += 4) {
                a0 = fmaf(G[(j + 0) * 96], sv[j + 0], a0);
                a1 = fmaf(G[(j + 1) * 96], sv[j + 1], a1);
                a2 = fmaf(G[(j + 2) * 96], sv[j + 2], a2);
                a3 = fmaf(G[(j + 3) * 96], sv[j + 3], a3);
            }
            part[tid] = (a0 + a1) + (a2 + a3);
            __syncthreads();                                         // sync3
            float snew = 0.f;
            if (tid < 96) {
                snew = ((part[tid] + part[96 + tid]) + (part[192 + tid] + part[288 + tid]))
                     + ((part[384 + tid] + part[480 + tid]) + (part[576 + tid] + part[672 + tid]));
            }
            float m2 = (tid < 96) ? snew : 0.f;
#pragma unroll
            for (int off = 16; off; off >>= 1) m2 = fmaxf(m2, __shfl_xor_sync(0xffffffffu, m2, off));
            if (tid < 96 && (tid & 31) == 0) wred2[tid >> 5] = m2;
            __syncthreads();                                         // sync4
            float mx = fmaxf(fmaxf(wred2[0], wred2[1]), wred2[2]);
            if (mx < 1e-30f) mx = 1.f;
            if (tid < 96) s_sh[tid] = snew / mx;
            Sacc += mc + logf(mx);
            __syncthreads();                                         // sync5
        }
    }

    // final: 11 per-tag dots against last-chunk rows (shared-resident)
    if (tid < 11) {
        float a0 = 0.f, a1 = 0.f, a2 = 0.f, a3 = 0.f;
#pragma unroll 4
        for (int j = 0; j < 96; j += 4) {
            a0 = fmaf(Rsh[(j + 0) * 12 + tid], st_sh[j + 0], a0);
            a1 = fmaf(Rsh[(j + 1) * 12 + tid], st_sh[j + 1], a1);
            a2 = fmaf(Rsh[(j + 2) * 12 + tid], st_sh[j + 2], a2);
            a3 = fmaf(Rsh[(j + 3) * 12 + tid], st_sh[j + 3], a3);
        }
        lv[tid] = logf((a0 + a1) + (a2 + a3));
    }
    __syncthreads();
    if (tid == 0) {
        float logZ = 11.f * (Sacc + mc);
        for (int t = 0; t < 11; t++) logZ += lv[t];
        out[0] = logZ - gold_sh;
    }
}

// ---------------- launch ----------------
extern "C" void kernel_launch(void* const* d_in, const int* in_sizes, int n_in,
                              void* d_out, int out_size)
{
    const float* feats = (const float*)d_in[0];
    const int*   tags  = (const int*)d_in[1];
    const float* Wd    = (const float*)d_in[2];
    const float* bd    = (const float*)d_in[3];
    const float* Wl    = (const float*)d_in[4];
    const float* bl    = (const float*)d_in[5];
    const float* Wr    = (const float*)d_in[6];
    const float* br    = (const float*)d_in[7];
    const float* Gl    = (const float*)d_in[8];
    const float* bgl   = (const float*)d_in[9];
    const float* Gr    = (const float*)d_in[10];
    const float* bgr   = (const float*)d_in[11];
    const float* Wt    = (const float*)d_in[12];
    const float* bt    = (const float*)d_in[13];
    const float* trans = (const float*)d_in[14];
    float* out = (float*)d_out;

    mega_kernel<<<NCTA, 256>>>(feats, Wd, bd, Wl, Wr, Gl, Gr,
                               bl, br, bgl, bgr, Wt, bt, trans);
    forward2<<<1, 768>>>(trans, bt, tags, out);
}

// round 8
// speedup vs baseline: 1.2762x; 1.0396x over previous
#include <cuda_runtime.h>
#include <cstdint>

#define L    768
#define D    256
#define NT   12
#define SPAN 8
#define NCTA 384

// ---------------- device scratch (static, no allocs) ----------------
__device__ __align__(16) float g_ht[8][L * D];        // ht per span-length diagonal
__device__ __align__(16) float g_BsL[1024 * 256];     // stacked interleaved [Wl|Gl], col'=4d+j
__device__ __align__(16) float g_BsR[1024 * 256];     // stacked interleaved [Wr|Gr]
__device__ __align__(16) float g_biasS[1024];         // stacked bias
__device__ __align__(16) float g_tagsc[8][L * NT];    // tag scores per diagonal (for gold)
__device__ __align__(16) float g_ex[L * NT * SPAN];   // exp(span scores) [i][t2][k]
__device__ __align__(16) float g_GT[11 * 96 * 96];    // chunk transfer matrices [c][j][o]
__device__ __align__(16) float g_sc[12 * 96];         // per-column log scales
__device__ __align__(16) float g_R[96 * 12];          // last chunk: A_767 rows [j][t2]
__device__ unsigned g_cnt;                            // grid barrier state (zero-init)
__device__ unsigned g_gen;

#define F2U(x) __float_as_uint(x)

__device__ __forceinline__ void mma_tf32(float& c0, float& c1, float& c2, float& c3,
                                         uint32_t a0, uint32_t a1, uint32_t a2, uint32_t a3,
                                         uint32_t b0, uint32_t b1)
{
    asm volatile("mma.sync.aligned.m16n8k8.row.col.f32.tf32.tf32.f32 "
                 "{%0,%1,%2,%3}, {%4,%5,%6,%7}, {%8,%9}, {%0,%1,%2,%3};\n"
                 : "+f"(c0), "+f"(c1), "+f"(c2), "+f"(c3)
                 : "r"(a0), "r"(a1), "r"(a2), "r"(a3), "r"(b0), "r"(b1));
}

__device__ __forceinline__ void cpa16(float* dst, const float* src)
{
    uint32_t d = (uint32_t)__cvta_generic_to_shared(dst);
    asm volatile("cp.async.cg.shared.global [%0], [%1], 16;\n" :: "r"(d), "l"(src));
}
#define CP_COMMIT() asm volatile("cp.async.commit_group;\n")
#define CP_WAIT(n)  asm volatile("cp.async.wait_group %0;\n" :: "n"(n))

// ---------------- software grid barrier (all NCTA co-resident by launch_bounds) ----
__device__ __forceinline__ void grid_bar()
{
    __syncthreads();
    if (threadIdx.x == 0) {
        __threadfence();
        unsigned gen = *(volatile unsigned*)&g_gen;
        if (atomicAdd(&g_cnt, 1u) == NCTA - 1u) {
            g_cnt = 0u;
            __threadfence();
            atomicAdd(&g_gen, 1u);
        } else {
            while (*(volatile unsigned*)&g_gen == gen) __nanosleep(32);
        }
        __threadfence();
    }
    __syncthreads();
}

#define POOL_FLOATS 9288

// ================== persistent mega kernel ==================
__global__ void __launch_bounds__(256, 3) mega_kernel(
    const float* __restrict__ feats, const float* __restrict__ Wd,
    const float* __restrict__ bd,
    const float* __restrict__ Wl, const float* __restrict__ Wr,
    const float* __restrict__ Gl, const float* __restrict__ Gr,
    const float* __restrict__ bl, const float* __restrict__ br,
    const float* __restrict__ bgl, const float* __restrict__ bgr,
    const float* __restrict__ Wt, const float* __restrict__ bt,
    const float* __restrict__ trans, const int* __restrict__ tags,
    float* __restrict__ out)
{
    __shared__ __align__(16) float pool[POOL_FLOATS];
    const int cta = blockIdx.x;
    const int tid = threadIdx.x;
    const int lane = tid & 31, warp = tid >> 5;
    const int g = lane >> 2, c = lane & 3;

    // ================= phase 0a: prep stacked weights + zero g_ex =================
    {
        int idx = cta * 256 + tid;
        if (idx < 65536) {
            int row = idx >> 6, k = (idx & 63) * 4;
            int d = row >> 2, j = row & 3;
            int srcrow = (j == 0) ? d : ((j - 1) * 256 + d);
            const float* sl4 = (j == 0) ? Wl : Gl;
            const float* sr4 = (j == 0) ? Wr : Gr;
            *(float4*)&g_BsL[(size_t)row * 256 + k] = *(const float4*)&sl4[(size_t)srcrow * 256 + k];
            *(float4*)&g_BsR[(size_t)row * 256 + k] = *(const float4*)&sr4[(size_t)srcrow * 256 + k];
        }
        if (idx < 1024) {
            int dd = idx >> 2, jj = idx & 3;
            g_biasS[idx] = (jj == 0) ? (bl[dd] + br[dd])
                                     : (bgl[(jj - 1) * 256 + dd] + bgr[(jj - 1) * 256 + dd]);
        }
        if (idx < L * NT * SPAN) g_ex[idx] = 0.f;
    }

    // ================= phase 0b: h = feats @ Wd^T + bd  (96 CTAs) =================
    if (cta < 96) {
        const int K = 512, NSTEP = 32;
        const int wm = warp & 3, wn = warp >> 2;
        const int m0 = (cta >> 3) * 64, n0 = (cta & 7) * 32;
        const int ar = tid >> 2, ac4 = (tid & 3) * 4;
        const int bi = tid & 127;
        const int brr = bi >> 2, bc4 = (bi & 3) * 4;
        const bool do_b = tid < 128;
        float acc[2][4] = {};

#pragma unroll
        for (int st = 0; st < 2; st++) {
            const int k0 = st * 16;
            cpa16(&pool[st * 1536 + ar * 24 + ac4], &feats[(size_t)(m0 + ar) * K + k0 + ac4]);
            if (do_b) cpa16(&pool[4608 + st * 768 + brr * 24 + bc4],
                            &Wd[(size_t)(n0 + brr) * K + k0 + bc4]);
            CP_COMMIT();
        }
        for (int step = 0; step < NSTEP; step++) {
            const int s = step % 3;
            if (step + 2 < NSTEP) {
                CP_WAIT(1);
                __syncthreads();
                const int k0 = (step + 2) * 16, s2 = (step + 2) % 3;
                cpa16(&pool[s2 * 1536 + ar * 24 + ac4], &feats[(size_t)(m0 + ar) * K + k0 + ac4]);
                if (do_b) cpa16(&pool[4608 + s2 * 768 + brr * 24 + bc4],
                                &Wd[(size_t)(n0 + brr) * K + k0 + bc4]);
                CP_COMMIT();
            } else {
                CP_WAIT(0);
                __syncthreads();
            }
#pragma unroll
            for (int kc = 0; kc < 2; kc++) {
                const int ko = kc * 8 + 2 * c;
                const float* p = &pool[s * 1536 + (wm * 16 + g) * 24 + ko];
                float2 fa0 = *(const float2*)p;
                float2 fa1 = *(const float2*)(p + 8 * 24);
#pragma unroll
                for (int ni = 0; ni < 2; ni++) {
                    const float* pb = &pool[4608 + s * 768 + (wn * 16 + ni * 8 + g) * 24 + ko];
                    float2 fb = *(const float2*)pb;
                    mma_tf32(acc[ni][0], acc[ni][1], acc[ni][2], acc[ni][3],
                             F2U(fa0.x), F2U(fa1.x), F2U(fa0.y), F2U(fa1.y),
                             F2U(fb.x), F2U(fb.y));
                }
            }
        }
#pragma unroll
        for (int ni = 0; ni < 2; ni++) {
            int col = n0 + wn * 16 + ni * 8 + 2 * c;
            float bv0 = bd[col], bv1 = bd[col + 1];
            int row0 = m0 + wm * 16 + g;
            g_ht[0][(size_t)row0 * 256 + col]           = acc[ni][0] + bv0;
            g_ht[0][(size_t)row0 * 256 + col + 1]       = acc[ni][1] + bv1;
            g_ht[0][(size_t)(row0 + 8) * 256 + col]     = acc[ni][2] + bv0;
            g_ht[0][(size_t)(row0 + 8) * 256 + col + 1] = acc[ni][3] + bv1;
        }
    }

    grid_bar();

    // ================= phase 1..7: fused dual GEMM + gate =================
    {
        const int wm = warp & 3, wn = warp >> 2;
        const int m0 = (cta >> 5) * 64, n0 = (cta & 31) * 32;
        const int ar = tid >> 2, ac4 = (tid & 3) * 4;
        const int bh = tid >> 7, bi = tid & 127;
        const int brr = bi >> 2, bc4 = (bi & 3) * 4;
        const float* bsrc = (bh ? g_BsR : g_BsL) + (size_t)n0 * 256;
        const int NSTEP = 16;

        for (int sl = 1; sl <= 7; sl++) {
            const int M = L - sl;
            const float* Aht = g_ht[sl - 1];
            float* htout = g_ht[sl];
            float acc[2][4] = {};

#pragma unroll
            for (int st = 0; st < 2; st++) {
                const int k0 = st * 16;
                cpa16(&pool[st * 1560 + ar * 24 + ac4], &Aht[(size_t)(m0 + ar) * 256 + k0 + ac4]);
                if (tid < 4) cpa16(&pool[st * 1560 + 64 * 24 + tid * 4],
                                   &Aht[(size_t)(m0 + 64) * 256 + k0 + tid * 4]);
                cpa16(&pool[4680 + st * 1536 + bh * 768 + brr * 24 + bc4],
                      &bsrc[(size_t)brr * 256 + k0 + bc4]);
                CP_COMMIT();
            }
            for (int step = 0; step < NSTEP; step++) {
                const int s = step % 3;
                if (step + 2 < NSTEP) {
                    CP_WAIT(1);
                    __syncthreads();
                    const int k0 = (step + 2) * 16, s2 = (step + 2) % 3;
                    cpa16(&pool[s2 * 1560 + ar * 24 + ac4],
                          &Aht[(size_t)(m0 + ar) * 256 + k0 + ac4]);
                    if (tid < 4) cpa16(&pool[s2 * 1560 + 64 * 24 + tid * 4],
                                       &Aht[(size_t)(m0 + 64) * 256 + k0 + tid * 4]);
                    cpa16(&pool[4680 + s2 * 1536 + bh * 768 + brr * 24 + bc4],
                          &bsrc[(size_t)brr * 256 + k0 + bc4]);
                    CP_COMMIT();
                } else {
                    CP_WAIT(0);
                    __syncthreads();
                }
#pragma unroll
                for (int kc = 0; kc < 2; kc++) {
                    const int ko = kc * 8 + 2 * c;
                    const float* p = &pool[s * 1560 + (wm * 16 + g) * 24 + ko];
                    float2 fa0 = *(const float2*)p;
                    float2 fa1 = *(const float2*)(p + 8 * 24);
                    float2 fr0 = *(const float2*)(p + 24);
                    float2 fr1 = *(const float2*)(p + 9 * 24);
#pragma unroll
                    for (int ni = 0; ni < 2; ni++) {
                        const int boff = (wn * 16 + ni * 8 + g) * 24 + ko;
                        float2 fbl = *(const float2*)&pool[4680 + s * 1536 + boff];
                        float2 fbr = *(const float2*)&pool[4680 + s * 1536 + 768 + boff];
                        mma_tf32(acc[ni][0], acc[ni][1], acc[ni][2], acc[ni][3],
                                 F2U(fa0.x), F2U(fa1.x), F2U(fa0.y), F2U(fa1.y),
                                 F2U(fbl.x), F2U(fbl.y));
                        mma_tf32(acc[ni][0], acc[ni][1], acc[ni][2], acc[ni][3],
                                 F2U(fr0.x), F2U(fr1.x), F2U(fr0.y), F2U(fr1.y),
                                 F2U(fbr.x), F2U(fbr.y));
                    }
                }
            }
#pragma unroll
            for (int ni = 0; ni < 2; ni++) {
                int colb = n0 + wn * 16 + ni * 8 + 2 * c;
                float b0 = g_biasS[colb], b1 = g_biasS[colb + 1];
                float z00 = acc[ni][0] + b0, z01 = acc[ni][1] + b1;
                float z10 = acc[ni][2] + b0, z11 = acc[ni][3] + b1;
                float w00 = __shfl_xor_sync(0xffffffffu, z00, 1);
                float w01 = __shfl_xor_sync(0xffffffffu, z01, 1);
                float w10 = __shfl_xor_sync(0xffffffffu, z10, 1);
                float w11 = __shfl_xor_sync(0xffffffffu, z11, 1);
                if ((c & 1) == 0) {
                    int d = colb >> 2;
                    int row0 = m0 + wm * 16 + g;
#pragma unroll
                    for (int rr = 0; rr < 2; rr++) {
                        int row = row0 + rr * 8;
                        if (row < M) {
                            float zh  = rr ? z10 : z00;
                            float zg0 = rr ? z11 : z01;
                            float zg1 = rr ? w10 : w00;
                            float zg2 = rr ? w11 : w01;
                            float lft = Aht[(size_t)row * 256 + d];
                            float rgt = Aht[(size_t)(row + 1) * 256 + d];
                            float hh = 4.f / (1.f + __expf(-zh)) - 2.f;
                            float mx = fmaxf(zg0, fmaxf(zg1, zg2));
                            float e0 = __expf(zg0 - mx), e1 = __expf(zg1 - mx),
                                  e2 = __expf(zg2 - mx);
                            float inv = 1.f / (e0 + e1 + e2);
                            htout[(size_t)row * 256 + d] =
                                (e0 * hh + e1 * lft + e2 * rgt) * inv;
                        }
                    }
                }
            }
            grid_bar();
        }
    }

    // ================= phase 8: tag scores + exp gather =================
    {
        for (int i = tid; i < NT * D; i += 256) pool[i] = Wt[i];
        __syncthreads();
#pragma unroll
        for (int rep = 0; rep < 2; rep++) {
            int gw = cta * 8 + warp + rep * 3072;
            int sl = gw / L;
            int pos = gw - sl * L;
            if (pos + sl < L) {
                const float* hp = g_ht[sl] + (size_t)pos * D;
                float4 h0 = *(const float4*)&hp[lane * 8];
                float4 h1 = *(const float4*)&hp[lane * 8 + 4];
                float hv[8] = {h0.x,h0.y,h0.z,h0.w,h1.x,h1.y,h1.z,h1.w};
                int i_end = pos + sl, kk = 7 - sl;
#pragma unroll
                for (int t = 0; t < NT; t++) {
                    const float* wp = &pool[t * D + lane * 8];
                    float4 w0 = *(const float4*)wp;
                    float4 w1 = *(const float4*)(wp + 4);
                    float s = hv[0]*w0.x + hv[1]*w0.y + hv[2]*w0.z + hv[3]*w0.w
                            + hv[4]*w1.x + hv[5]*w1.y + hv[6]*w1.z + hv[7]*w1.w;
#pragma unroll
                    for (int o = 16; o; o >>= 1) s += __shfl_xor_sync(0xffffffffu, s, o);
                    if (lane == 0) {
                        float val = s + bt[t];
                        g_tagsc[sl][pos * NT + t] = val;
                        g_ex[((size_t)i_end * NT + t) * SPAN + kk] = __expf(val);
                    }
                }
            }
        }
    }

    grid_bar();

    // ================= phase 9: chunk transfer matrices (basis runs) =================
    if (warp < 3) {
        const int run = cta * 3 + warp;            // 0..1151
        const int chunk = run / 96, j = run - chunk * 96;
        const int slotj = j / 12, tj = j - slotj * 12;
        const int t2 = (lane < 12) ? lane : 11;

        float eTc[12];
#pragma unroll
        for (int t1 = 0; t1 < 12; t1++) eTc[t1] = __expf(trans[t1 * 12 + t2]);

        float Cw[8];
#pragma unroll
        for (int k = 0; k < 8; k++) Cw[k] = 0.f;
        if (lane == tj) Cw[slotj] = 1.f;
        float sc = 0.f;
        float lastA = 0.f;

        const float4* exb = (const float4*)(g_ex + ((size_t)(chunk * 64) * 12 + t2) * 8);
        float4 c0 = exb[0], c1 = exb[1];
        float4 n0 = exb[24], n1 = exb[25];

        for (int blk = 0; blk < 8; blk++) {
#pragma unroll
            for (int u = 0; u < 8; u++) {
                const int li = blk * 8 + u;
                float4 f0 = c0, f1 = c1;
                c0 = n0; c1 = n1;
                if (li + 2 < 64) {
                    n0 = exb[(li + 2) * 24];
                    n1 = exb[(li + 2) * 24 + 1];
                }
                float e0=f0.x,e1=f0.y,e2=f0.z,e3=f0.w,e4=f1.x,e5=f1.y,e6=f1.z,e7=f1.w;
                float v01 = fmaf(e1, Cw[(u + 1) & 7], e0 * Cw[(u + 0) & 7]);
                float v23 = fmaf(e3, Cw[(u + 3) & 7], e2 * Cw[(u + 2) & 7]);
                float v45 = fmaf(e5, Cw[(u + 5) & 7], e4 * Cw[(u + 4) & 7]);
                float v6  = e6 * Cw[(u + 6) & 7];
                float A = fmaf(e7, Cw[(u + 7) & 7], (v01 + v23) + (v45 + v6));
                lastA = A;
                float bnA = 0.f, bnB = 0.f;
#pragma unroll
                for (int t1 = 0; t1 < 6; t1++) {
                    bnA = fmaf(eTc[t1],     __shfl_sync(0xffffffffu, A, t1),     bnA);
                    bnB = fmaf(eTc[t1 + 6], __shfl_sync(0xffffffffu, A, t1 + 6), bnB);
                }
                Cw[u] = bnA + bnB;
            }
            if (blk != 7) {
                float m = (lane < 12) ? Cw[7] : 0.f;
#pragma unroll
                for (int o = 16; o; o >>= 1) m = fmaxf(m, __shfl_xor_sync(0xffffffffu, m, o));
                if (m < 1e-30f) m = 1.f;
                float inv = 1.f / m;
#pragma unroll
                for (int k = 0; k < 8; k++) Cw[k] *= inv;
                sc += __logf(m);
            }
        }

        if (chunk < 11) {
            if (lane < 12) {
#pragma unroll
                for (int slot = 0; slot < 8; slot++)
                    g_GT[((size_t)chunk * 96 + j) * 96 + slot * 12 + lane] = Cw[slot];
            }
            if (lane == 0) g_sc[chunk * 96 + j] = sc;
        } else {
            if (lane < 12) g_R[j * 12 + lane] = lastA;
            if (lane == 0) g_sc[11 * 96 + j] = sc;
        }
    }

    grid_bar();
    if (cta != 0) return;

    // ================= phase 10 (CTA 0 only): gold + chunk matvec chain =================
    {
        // pool aliases (phase 8/9 data in pool is dead now)
        float* s_sh   = pool;            // 96
        float* st_sh  = pool + 96;       // 96
        float* lv     = pool + 192;      // 11
        float* wred   = pool + 204;      // 3
        float* wred2  = pool + 208;      // 3
        float* gold_sh= pool + 212;      // 1
        float* scall  = pool + 256;      // 1152
        float* Rsh    = pool + 1472;     // 1152
        float* part   = pool + 2688;     // 768

        __syncthreads();
        for (int i = tid; i < 1152; i += 256) { scall[i] = g_sc[i]; Rsh[i] = g_R[i]; }

        if (warp == 0) {
            float gold = 0.f;
            for (int s = lane; s < 96; s += 32) {
                int i  = tags[s * 4 + 0];
                int j  = tags[s * 4 + 1];
                int pr = tags[s * 4 + 2];
                int t  = tags[s * 4 + 3];
                int sl = j - i;
                float base = (sl >= 0 && sl < SPAN && i >= 0 && i + sl < L)
                           ? g_tagsc[sl][i * NT + t] : bt[t];
                gold += base + trans[pr * NT + t];
            }
#pragma unroll
            for (int o = 16; o; o >>= 1) gold += __shfl_xor_sync(0xffffffffu, gold, o);
            if (lane == 0) gold_sh[0] = gold;
        }
        if (tid < 96) s_sh[tid] = (tid >= 84) ? expf(trans[10 * 12 + (tid - 84)]) : 0.f;
        __syncthreads();

        const int p8 = warp;             // 0..7
        float Sacc = 0.f, mc = 0.f;
        for (int cch = 0; cch < 12; cch++) {
            float m = (tid < 96) ? scall[cch * 96 + tid] : -3e38f;
#pragma unroll
            for (int off = 16; off; off >>= 1) m = fmaxf(m, __shfl_xor_sync(0xffffffffu, m, off));
            if (tid < 96 && lane == 0) wred[warp] = m;
            __syncthreads();
            mc = fmaxf(fmaxf(wred[0], wred[1]), wred[2]);
            if (tid < 96) st_sh[tid] = s_sh[tid] * expf(scall[cch * 96 + tid] - mc);
            __syncthreads();

            if (cch < 11) {
                // thread (p8, lane): 3 output columns o = lane, lane+32, lane+64
                const float* G = g_GT + (size_t)cch * 9216 + (size_t)(p8 * 12) * 96;
                const float* sv = &st_sh[p8 * 12];
                float a0 = 0.f, a1 = 0.f, a2 = 0.f;
#pragma unroll
                for (int j = 0; j < 12; j++) {
                    float svj = sv[j];
                    a0 = fmaf(G[j * 96 + lane],      svj, a0);
                    a1 = fmaf(G[j * 96 + lane + 32], svj, a1);
                    a2 = fmaf(G[j * 96 + lane + 64], svj, a2);
                }
                part[p8 * 96 + lane]      = a0;
                part[p8 * 96 + lane + 32] = a1;
                part[p8 * 96 + lane + 64] = a2;
                __syncthreads();
                float snew = 0.f;
                if (tid < 96) {
                    snew = ((part[tid] + part[96 + tid]) + (part[192 + tid] + part[288 + tid]))
                         + ((part[384 + tid] + part[480 + tid]) + (part[576 + tid] + part[672 + tid]));
                }
                float m2 = (tid < 96) ? snew : 0.f;
#pragma unroll
                for (int off = 16; off; off >>= 1) m2 = fmaxf(m2, __shfl_xor_sync(0xffffffffu, m2, off));
                if (tid < 96 && lane == 0) wred2[warp] = m2;
                __syncthreads();
                float mx = fmaxf(fmaxf(wred2[0], wred2[1]), wred2[2]);
                if (mx < 1e-30f) mx = 1.f;
                if (tid < 96) s_sh[tid] = snew / mx;
                Sacc += mc + logf(mx);
                __syncthreads();
            }
        }

        if (tid < 11) {
            float a0 = 0.f, a1 = 0.f, a2 = 0.f, a3 = 0.f;
#pragma unroll 4
            for (int j = 0; j < 96; j += 4) {
                a0 = fmaf(Rsh[(j + 0) * 12 + tid], st_sh[j + 0], a0);
                a1 = fmaf(Rsh[(j + 1) * 12 + tid], st_sh[j + 1], a1);
                a2 = fmaf(Rsh[(j + 2) * 12 + tid], st_sh[j + 2], a2);
                a3 = fmaf(Rsh[(j + 3) * 12 + tid], st_sh[j + 3], a3);
            }
            lv[tid] = logf((a0 + a1) + (a2 + a3));
        }
        __syncthreads();
        if (tid == 0) {
            float logZ = 11.f * (Sacc + mc);
            for (int t = 0; t < 11; t++) logZ += lv[t];
            out[0] = logZ - gold_sh[0];
        }
    }
}

// ---------------- launch ----------------
extern "C" void kernel_launch(void* const* d_in, const int* in_sizes, int n_in,
                              void* d_out, int out_size)
{
    const float* feats = (const float*)d_in[0];
    const int*   tags  = (const int*)d_in[1];
    const float* Wd    = (const float*)d_in[2];
    const float* bd    = (const float*)d_in[3];
    const float* Wl    = (const float*)d_in[4];
    const float* bl    = (const float*)d_in[5];
    const float* Wr    = (const float*)d_in[6];
    const float* br    = (const float*)d_in[7];
    const float* Gl    = (const float*)d_in[8];
    const float* bgl   = (const float*)d_in[9];
    const float* Gr    = (const float*)d_in[10];
    const float* bgr   = (const float*)d_in[11];
    const float* Wt    = (const float*)d_in[12];
    const float* bt    = (const float*)d_in[13];
    const float* trans = (const float*)d_in[14];
    float* out = (float*)d_out;

    mega_kernel<<<NCTA, 256>>>(feats, Wd, bd, Wl, Wr, Gl, Gr,
                               bl, br, bgl, bgr, Wt, bt, trans, tags, out);
}

// round 9
// speedup vs baseline: 1.4518x; 1.1376x over previous
#include <cuda_runtime.h>
#include <cstdint>

#define L    768
#define D    256
#define NT   12
#define SPAN 8
#define NCTA 384

// ---------------- device scratch (static, no allocs) ----------------
__device__ __align__(16) float g_ht[8][L * D];        // ht per span-length diagonal
__device__ __align__(16) float g_BsL[1024 * 256];     // stacked interleaved [Wl|Gl], col'=4d+j
__device__ __align__(16) float g_BsR[1024 * 256];     // stacked interleaved [Wr|Gr]
__device__ __align__(16) float g_biasS[1024];         // stacked bias
__device__ __align__(16) float g_tagsc[8][L * NT];    // tag scores per diagonal (for gold)
__device__ __align__(16) float g_ex[L * NT * SPAN];   // exp(span scores) [i][t2][k]
__device__ __align__(16) float g_GT[11 * 96 * 96];    // chunk transfer matrices [c][j][o]
__device__ __align__(16) float g_sc[12 * 96];         // per-column log scales
__device__ __align__(16) float g_R[96 * 12];          // last chunk: A_767 rows [j][t2]
__device__ unsigned g_cnt;                            // grid barrier state (zero-init)
__device__ unsigned g_gen;

#define F2U(x) __float_as_uint(x)

__device__ __forceinline__ void mma_tf32(float& c0, float& c1, float& c2, float& c3,
                                         uint32_t a0, uint32_t a1, uint32_t a2, uint32_t a3,
                                         uint32_t b0, uint32_t b1)
{
    asm volatile("mma.sync.aligned.m16n8k8.row.col.f32.tf32.tf32.f32 "
                 "{%0,%1,%2,%3}, {%4,%5,%6,%7}, {%8,%9}, {%0,%1,%2,%3};\n"
                 : "+f"(c0), "+f"(c1), "+f"(c2), "+f"(c3)
                 : "r"(a0), "r"(a1), "r"(a2), "r"(a3), "r"(b0), "r"(b1));
}

__device__ __forceinline__ void cpa16(float* dst, const float* src)
{
    uint32_t d = (uint32_t)__cvta_generic_to_shared(dst);
    asm volatile("cp.async.cg.shared.global [%0], [%1], 16;\n" :: "r"(d), "l"(src));
}
#define CP_COMMIT() asm volatile("cp.async.commit_group;\n")
#define CP_WAIT(n)  asm volatile("cp.async.wait_group %0;\n" :: "n"(n))

// ---------------- software grid barrier (all NCTA co-resident by launch_bounds) ----
__device__ __forceinline__ void grid_bar()
{
    __syncthreads();
    if (threadIdx.x == 0) {
        __threadfence();
        unsigned gen = *(volatile unsigned*)&g_gen;
        if (atomicAdd(&g_cnt, 1u) == NCTA - 1u) {
            g_cnt = 0u;
            __threadfence();
            atomicAdd(&g_gen, 1u);
        } else {
            while (*(volatile unsigned*)&g_gen == gen) __nanosleep(32);
        }
        __threadfence();
    }
    __syncthreads();
}

// ---------------- shared pool layout (BK=32, 2-stage) ----------------
// AS(s)  = pool + s*2600          (65 rows x stride 40)
// BS(s,h)= pool + 5200 + s*2560 + h*1280   (32 rows x stride 40 per half)
#define SA 40
#define POOL_FLOATS 10320
#define AS_OFF(s)    ((s) * 2600)
#define BS_OFF(s, h) (5200 + (s) * 2560 + (h) * 1280)

// ================== persistent mega kernel ==================
__global__ void __launch_bounds__(256, 3) mega_kernel(
    const float* __restrict__ feats, const float* __restrict__ Wd,
    const float* __restrict__ bd,
    const float* __restrict__ Wl, const float* __restrict__ Wr,
    const float* __restrict__ Gl, const float* __restrict__ Gr,
    const float* __restrict__ bl, const float* __restrict__ br,
    const float* __restrict__ bgl, const float* __restrict__ bgr,
    const float* __restrict__ Wt, const float* __restrict__ bt,
    const float* __restrict__ trans, const int* __restrict__ tags,
    float* __restrict__ out)
{
    __shared__ __align__(16) float pool[POOL_FLOATS];
    const int cta = blockIdx.x;
    const int tid = threadIdx.x;
    const int lane = tid & 31, warp = tid >> 5;
    const int g = lane >> 2, c = lane & 3;

    // ================= phase 0a: prep stacked weights + zero g_ex =================
    {
        int idx = cta * 256 + tid;
        if (idx < 65536) {
            int row = idx >> 6, k = (idx & 63) * 4;
            int d = row >> 2, j = row & 3;
            int srcrow = (j == 0) ? d : ((j - 1) * 256 + d);
            const float* sl4 = (j == 0) ? Wl : Gl;
            const float* sr4 = (j == 0) ? Wr : Gr;
            *(float4*)&g_BsL[(size_t)row * 256 + k] = *(const float4*)&sl4[(size_t)srcrow * 256 + k];
            *(float4*)&g_BsR[(size_t)row * 256 + k] = *(const float4*)&sr4[(size_t)srcrow * 256 + k];
        }
        if (idx < 1024) {
            int dd = idx >> 2, jj = idx & 3;
            g_biasS[idx] = (jj == 0) ? (bl[dd] + br[dd])
                                     : (bgl[(jj - 1) * 256 + dd] + bgr[(jj - 1) * 256 + dd]);
        }
        if (idx < L * NT * SPAN) g_ex[idx] = 0.f;
    }

    // ================= phase 0b: h = feats @ Wd^T + bd  (96 CTAs, BK=32) =========
    if (cta < 96) {
        const int K = 512, NSTEP = 16;
        const int wm = warp & 3, wn = warp >> 2;
        const int m0 = (cta >> 3) * 64, n0 = (cta & 7) * 32;
        // A: 512 chunks (64 rows x 8 f4); thread does tid, tid+256
        const int ar0 = tid >> 3,          ac0 = (tid & 7) * 4;
        const int ar1 = (tid + 256) >> 3,  ac1 = ((tid + 256) & 7) * 4;
        // B: 256 chunks; thread does tid
        const int brr = tid >> 3, bcc = (tid & 7) * 4;
        float acc[2][4] = {};

        // prologue: stage 0
        cpa16(&pool[AS_OFF(0) + ar0 * SA + ac0], &feats[(size_t)(m0 + ar0) * K + ac0]);
        cpa16(&pool[AS_OFF(0) + ar1 * SA + ac1], &feats[(size_t)(m0 + ar1) * K + ac1]);
        cpa16(&pool[BS_OFF(0, 0) + brr * SA + bcc], &Wd[(size_t)(n0 + brr) * K + bcc]);
        CP_COMMIT();

#pragma unroll
        for (int step = 0; step < NSTEP; step++) {
            const int s = step & 1;
            CP_WAIT(0);
            __syncthreads();
            if (step + 1 < NSTEP) {
                const int k0 = (step + 1) * 32, s2 = s ^ 1;
                cpa16(&pool[AS_OFF(s2) + ar0 * SA + ac0], &feats[(size_t)(m0 + ar0) * K + k0 + ac0]);
                cpa16(&pool[AS_OFF(s2) + ar1 * SA + ac1], &feats[(size_t)(m0 + ar1) * K + k0 + ac1]);
                cpa16(&pool[BS_OFF(s2, 0) + brr * SA + bcc], &Wd[(size_t)(n0 + brr) * K + k0 + bcc]);
                CP_COMMIT();
            }
#pragma unroll
            for (int kc = 0; kc < 4; kc++) {
                const int ko = kc * 8 + 2 * c;
                const float* p = &pool[AS_OFF(s) + (wm * 16 + g) * SA + ko];
                float2 fa0 = *(const float2*)p;
                float2 fa1 = *(const float2*)(p + 8 * SA);
#pragma unroll
                for (int ni = 0; ni < 2; ni++) {
                    const float* pb = &pool[BS_OFF(s, 0) + (wn * 16 + ni * 8 + g) * SA + ko];
                    float2 fb = *(const float2*)pb;
                    mma_tf32(acc[ni][0], acc[ni][1], acc[ni][2], acc[ni][3],
                             F2U(fa0.x), F2U(fa1.x), F2U(fa0.y), F2U(fa1.y),
                             F2U(fb.x), F2U(fb.y));
                }
            }
        }
#pragma unroll
        for (int ni = 0; ni < 2; ni++) {
            int col = n0 + wn * 16 + ni * 8 + 2 * c;
            float bv0 = bd[col], bv1 = bd[col + 1];
            int row0 = m0 + wm * 16 + g;
            g_ht[0][(size_t)row0 * 256 + col]           = acc[ni][0] + bv0;
            g_ht[0][(size_t)row0 * 256 + col + 1]       = acc[ni][1] + bv1;
            g_ht[0][(size_t)(row0 + 8) * 256 + col]     = acc[ni][2] + bv0;
            g_ht[0][(size_t)(row0 + 8) * 256 + col + 1] = acc[ni][3] + bv1;
        }
    }

    grid_bar();

    // ================= phase 1..7: fused dual GEMM + gate (BK=32, 2-stage) =======
    {
        const int wm = warp & 3, wn = warp >> 2;
        const int m0 = (cta >> 5) * 64, n0 = (cta & 31) * 32;
        // A: 520 chunks (65 rows x 8 f4): tid, tid+256, tid<8: 512+tid
        const int ar0 = tid >> 3,          ac0 = (tid & 7) * 4;
        const int ar1 = (tid + 256) >> 3,  ac1 = ((tid + 256) & 7) * 4;
        const int ar2 = (tid + 512) >> 3,  ac2 = ((tid + 512) & 7) * 4;   // tid<8 only
        // B: half bh, chunks bi and bi+128 of that half's 256
        const int bh = tid >> 7, bi = tid & 127;
        const int br0 = bi >> 3,          bc0 = (bi & 7) * 4;
        const int br1 = (bi + 128) >> 3,  bc1 = ((bi + 128) & 7) * 4;
        const float* bsrc = (bh ? g_BsR : g_BsL) + (size_t)n0 * 256;
        const int NSTEP = 8;

        for (int sl = 1; sl <= 7; sl++) {
            const int M = L - sl;
            const float* Aht = g_ht[sl - 1];
            float* htout = g_ht[sl];
            float acc[2][4] = {};

            // prologue: stage 0
            cpa16(&pool[AS_OFF(0) + ar0 * SA + ac0], &Aht[(size_t)(m0 + ar0) * 256 + ac0]);
            cpa16(&pool[AS_OFF(0) + ar1 * SA + ac1], &Aht[(size_t)(m0 + ar1) * 256 + ac1]);
            if (tid < 8)
                cpa16(&pool[AS_OFF(0) + ar2 * SA + ac2], &Aht[(size_t)(m0 + ar2) * 256 + ac2]);
            cpa16(&pool[BS_OFF(0, bh) + br0 * SA + bc0], &bsrc[(size_t)br0 * 256 + bc0]);
            cpa16(&pool[BS_OFF(0, bh) + br1 * SA + bc1], &bsrc[(size_t)br1 * 256 + bc1]);
            CP_COMMIT();

#pragma unroll
            for (int step = 0; step < NSTEP; step++) {
                const int s = step & 1;
                CP_WAIT(0);
                __syncthreads();
                if (step + 1 < NSTEP) {
                    const int k0 = (step + 1) * 32, s2 = s ^ 1;
                    cpa16(&pool[AS_OFF(s2) + ar0 * SA + ac0],
                          &Aht[(size_t)(m0 + ar0) * 256 + k0 + ac0]);
                    cpa16(&pool[AS_OFF(s2) + ar1 * SA + ac1],
                          &Aht[(size_t)(m0 + ar1) * 256 + k0 + ac1]);
                    if (tid < 8)
                        cpa16(&pool[AS_OFF(s2) + ar2 * SA + ac2],
                              &Aht[(size_t)(m0 + ar2) * 256 + k0 + ac2]);
                    cpa16(&pool[BS_OFF(s2, bh) + br0 * SA + bc0],
                          &bsrc[(size_t)br0 * 256 + k0 + bc0]);
                    cpa16(&pool[BS_OFF(s2, bh) + br1 * SA + bc1],
                          &bsrc[(size_t)br1 * 256 + k0 + bc1]);
                    CP_COMMIT();
                }
#pragma unroll
                for (int kc = 0; kc < 4; kc++) {
                    const int ko = kc * 8 + 2 * c;
                    const float* p = &pool[AS_OFF(s) + (wm * 16 + g) * SA + ko];
                    float2 fa0 = *(const float2*)p;
                    float2 fa1 = *(const float2*)(p + 8 * SA);
                    float2 fr0 = *(const float2*)(p + SA);       // shifted one row: r
                    float2 fr1 = *(const float2*)(p + 9 * SA);
#pragma unroll
                    for (int ni = 0; ni < 2; ni++) {
                        const int boff = (wn * 16 + ni * 8 + g) * SA + ko;
                        float2 fbl = *(const float2*)&pool[BS_OFF(s, 0) + boff];
                        float2 fbr = *(const float2*)&pool[BS_OFF(s, 1) + boff];
                        mma_tf32(acc[ni][0], acc[ni][1], acc[ni][2], acc[ni][3],
                                 F2U(fa0.x), F2U(fa1.x), F2U(fa0.y), F2U(fa1.y),
                                 F2U(fbl.x), F2U(fbl.y));
                        mma_tf32(acc[ni][0], acc[ni][1], acc[ni][2], acc[ni][3],
                                 F2U(fr0.x), F2U(fr1.x), F2U(fr0.y), F2U(fr1.y),
                                 F2U(fbr.x), F2U(fbr.y));
                    }
                }
            }
            // ---- fused gate epilogue ----
#pragma unroll
            for (int ni = 0; ni < 2; ni++) {
                int colb = n0 + wn * 16 + ni * 8 + 2 * c;
                float b0 = g_biasS[colb], b1 = g_biasS[colb + 1];
                float z00 = acc[ni][0] + b0, z01 = acc[ni][1] + b1;
                float z10 = acc[ni][2] + b0, z11 = acc[ni][3] + b1;
                float w00 = __shfl_xor_sync(0xffffffffu, z00, 1);
                float w01 = __shfl_xor_sync(0xffffffffu, z01, 1);
                float w10 = __shfl_xor_sync(0xffffffffu, z10, 1);
                float w11 = __shfl_xor_sync(0xffffffffu, z11, 1);
                if ((c & 1) == 0) {
                    int d = colb >> 2;
                    int row0 = m0 + wm * 16 + g;
#pragma unroll
                    for (int rr = 0; rr < 2; rr++) {
                        int row = row0 + rr * 8;
                        if (row < M) {
                            float zh  = rr ? z10 : z00;
                            float zg0 = rr ? z11 : z01;
                            float zg1 = rr ? w10 : w00;
                            float zg2 = rr ? w11 : w01;
                            float lft = Aht[(size_t)row * 256 + d];
                            float rgt = Aht[(size_t)(row + 1) * 256 + d];
                            float hh = 4.f / (1.f + __expf(-zh)) - 2.f;
                            float mx = fmaxf(zg0, fmaxf(zg1, zg2));
                            float e0 = __expf(zg0 - mx), e1 = __expf(zg1 - mx),
                                  e2 = __expf(zg2 - mx);
                            float inv = 1.f / (e0 + e1 + e2);
                            htout[(size_t)row * 256 + d] =
                                (e0 * hh + e1 * lft + e2 * rgt) * inv;
                        }
                    }
                }
            }
            grid_bar();
        }
    }

    // ================= phase 8: tag scores + exp gather =================
    {
        for (int i = tid; i < NT * D; i += 256) pool[i] = Wt[i];
        __syncthreads();
#pragma unroll
        for (int rep = 0; rep < 2; rep++) {
            int gw = cta * 8 + warp + rep * 3072;
            int sl = gw / L;
            int pos = gw - sl * L;
            if (pos + sl < L) {
                const float* hp = g_ht[sl] + (size_t)pos * D;
                float4 h0 = *(const float4*)&hp[lane * 8];
                float4 h1 = *(const float4*)&hp[lane * 8 + 4];
                float hv[8] = {h0.x,h0.y,h0.z,h0.w,h1.x,h1.y,h1.z,h1.w};
                int i_end = pos + sl, kk = 7 - sl;
#pragma unroll
                for (int t = 0; t < NT; t++) {
                    const float* wp = &pool[t * D + lane * 8];
                    float4 w0 = *(const float4*)wp;
                    float4 w1 = *(const float4*)(wp + 4);
                    float s = hv[0]*w0.x + hv[1]*w0.y + hv[2]*w0.z + hv[3]*w0.w
                            + hv[4]*w1.x + hv[5]*w1.y + hv[6]*w1.z + hv[7]*w1.w;
#pragma unroll
                    for (int o = 16; o; o >>= 1) s += __shfl_xor_sync(0xffffffffu, s, o);
                    if (lane == 0) {
                        float val = s + bt[t];
                        g_tagsc[sl][pos * NT + t] = val;
                        g_ex[((size_t)i_end * NT + t) * SPAN + kk] = __expf(val);
                    }
                }
            }
        }
    }

    grid_bar();

    // ================= phase 9: chunk transfer matrices (basis runs) =================
    if (warp < 3) {
        const int run = cta * 3 + warp;            // 0..1151
        const int chunk = run / 96, j = run - chunk * 96;
        const int slotj = j / 12, tj = j - slotj * 12;
        const int t2 = (lane < 12) ? lane : 11;

        float eTc[12];
#pragma unroll
        for (int t1 = 0; t1 < 12; t1++) eTc[t1] = __expf(trans[t1 * 12 + t2]);

        float Cw[8];
#pragma unroll
        for (int k = 0; k < 8; k++) Cw[k] = 0.f;
        if (lane == tj) Cw[slotj] = 1.f;
        float sc = 0.f;
        float lastA = 0.f;

        const float4* exb = (const float4*)(g_ex + ((size_t)(chunk * 64) * 12 + t2) * 8);
        float4 c0 = exb[0], c1 = exb[1];
        float4 n0 = exb[24], n1 = exb[25];

        for (int blk = 0; blk < 8; blk++) {
#pragma unroll
            for (int u = 0; u < 8; u++) {
                const int li = blk * 8 + u;
                float4 f0 = c0, f1 = c1;
                c0 = n0; c1 = n1;
                if (li + 2 < 64) {
                    n0 = exb[(li + 2) * 24];
                    n1 = exb[(li + 2) * 24 + 1];
                }
                float e0=f0.x,e1=f0.y,e2=f0.z,e3=f0.w,e4=f1.x,e5=f1.y,e6=f1.z,e7=f1.w;
                float v01 = fmaf(e1, Cw[(u + 1) & 7], e0 * Cw[(u + 0) & 7]);
                float v23 = fmaf(e3, Cw[(u + 3) & 7], e2 * Cw[(u + 2) & 7]);
                float v45 = fmaf(e5, Cw[(u + 5) & 7], e4 * Cw[(u + 4) & 7]);
                float v6  = e6 * Cw[(u + 6) & 7];
                float A = fmaf(e7, Cw[(u + 7) & 7], (v01 + v23) + (v45 + v6));
                lastA = A;
                float bnA = 0.f, bnB = 0.f;
#pragma unroll
                for (int t1 = 0; t1 < 6; t1++) {
                    bnA = fmaf(eTc[t1],     __shfl_sync(0xffffffffu, A, t1),     bnA);
                    bnB = fmaf(eTc[t1 + 6], __shfl_sync(0xffffffffu, A, t1 + 6), bnB);
                }
                Cw[u] = bnA + bnB;
            }
            if (blk != 7) {
                float m = (lane < 12) ? Cw[7] : 0.f;
#pragma unroll
                for (int o = 16; o; o >>= 1) m = fmaxf(m, __shfl_xor_sync(0xffffffffu, m, o));
                if (m < 1e-30f) m = 1.f;
                float inv = 1.f / m;
#pragma unroll
                for (int k = 0; k < 8; k++) Cw[k] *= inv;
                sc += __logf(m);
            }
        }

        if (chunk < 11) {
            if (lane < 12) {
#pragma unroll
                for (int slot = 0; slot < 8; slot++)
                    g_GT[((size_t)chunk * 96 + j) * 96 + slot * 12 + lane] = Cw[slot];
            }
            if (lane == 0) g_sc[chunk * 96 + j] = sc;
        } else {
            if (lane < 12) g_R[j * 12 + lane] = lastA;
            if (lane == 0) g_sc[11 * 96 + j] = sc;
        }
    }

    grid_bar();
    if (cta != 0) return;

    // ================= phase 10 (CTA 0 only): gold + chunk matvec chain =================
    {
        float* s_sh   = pool;            // 96
        float* st_sh  = pool + 96;       // 96
        float* lv     = pool + 192;      // 11
        float* wred   = pool + 204;      // 3
        float* wred2  = pool + 208;      // 3
        float* gold_sh= pool + 212;      // 1
        float* scall  = pool + 256;      // 1152
        float* Rsh    = pool + 1472;     // 1152
        float* part   = pool + 2688;     // 768

        __syncthreads();
        for (int i = tid; i < 1152; i += 256) { scall[i] = g_sc[i]; Rsh[i] = g_R[i]; }

        if (warp == 0) {
            float gold = 0.f;
            for (int s = lane; s < 96; s += 32) {
                int i  = tags[s * 4 + 0];
                int j  = tags[s * 4 + 1];
                int pr = tags[s * 4 + 2];
                int t  = tags[s * 4 + 3];
                int sl = j - i;
                float base = (sl >= 0 && sl < SPAN && i >= 0 && i + sl < L)
                           ? g_tagsc[sl][i * NT + t] : bt[t];
                gold += base + trans[pr * NT + t];
            }
#pragma unroll
            for (int o = 16; o; o >>= 1) gold += __shfl_xor_sync(0xffffffffu, gold, o);
            if (lane == 0) gold_sh[0] = gold;
        }
        if (tid < 96) s_sh[tid] = (tid >= 84) ? expf(trans[10 * 12 + (tid - 84)]) : 0.f;
        __syncthreads();

        const int p8 = warp;
        float Sacc = 0.f, mc = 0.f;
        for (int cch = 0; cch < 12; cch++) {
            float m = (tid < 96) ? scall[cch * 96 + tid] : -3e38f;
#pragma unroll
            for (int off = 16; off; off >>= 1) m = fmaxf(m, __shfl_xor_sync(0xffffffffu, m, off));
            if (tid < 96 && lane == 0) wred[warp] = m;
            __syncthreads();
            mc = fmaxf(fmaxf(wred[0], wred[1]), wred[2]);
            if (tid < 96) st_sh[tid] = s_sh[tid] * expf(scall[cch * 96 + tid] - mc);
            __syncthreads();

            if (cch < 11) {
                const float* G = g_GT + (size_t)cch * 9216 + (size_t)(p8 * 12) * 96;
                const float* sv = &st_sh[p8 * 12];
                float a0 = 0.f, a1 = 0.f, a2 = 0.f;
#pragma unroll
                for (int j = 0; j < 12; j++) {
                    float svj = sv[j];
                    a0 = fmaf(G[j * 96 + lane],      svj, a0);
                    a1 = fmaf(G[j * 96 + lane + 32], svj, a1);
                    a2 = fmaf(G[j * 96 + lane + 64], svj, a2);
                }
                part[p8 * 96 + lane]      = a0;
                part[p8 * 96 + lane + 32] = a1;
                part[p8 * 96 + lane + 64] = a2;
                __syncthreads();
                float snew = 0.f;
                if (tid < 96) {
                    snew = ((part[tid] + part[96 + tid]) + (part[192 + tid] + part[288 + tid]))
                         + ((part[384 + tid] + part[480 + tid]) + (part[576 + tid] + part[672 + tid]));
                }
                float m2 = (tid < 96) ? snew : 0.f;
#pragma unroll
                for (int off = 16; off; off >>= 1) m2 = fmaxf(m2, __shfl_xor_sync(0xffffffffu, m2, off));
                if (tid < 96 && lane == 0) wred2[warp] = m2;
                __syncthreads();
                float mx = fmaxf(fmaxf(wred2[0], wred2[1]), wred2[2]);
                if (mx < 1e-30f) mx = 1.f;
                if (tid < 96) s_sh[tid] = snew / mx;
                Sacc += mc + logf(mx);
                __syncthreads();
            }
        }

        if (tid < 11) {
            float a0 = 0.f, a1 = 0.f, a2 = 0.f, a3 = 0.f;
#pragma unroll 4
            for (int j = 0; j < 96; j += 4) {
                a0 = fmaf(Rsh[(j + 0) * 12 + tid], st_sh[j + 0], a0);
                a1 = fmaf(Rsh[(j + 1) * 12 + tid], st_sh[j + 1], a1);
                a2 = fmaf(Rsh[(j + 2) * 12 + tid], st_sh[j + 2], a2);
                a3 = fmaf(Rsh[(j + 3) * 12 + tid], st_sh[j + 3], a3);
            }
            lv[tid] = logf((a0 + a1) + (a2 + a3));
        }
        __syncthreads();
        if (tid == 0) {
            float logZ = 11.f * (Sacc + mc);
            for (int t = 0; t < 11; t++) logZ += lv[t];
            out[0] = logZ - gold_sh[0];
        }
    }
}

// ---------------- launch ----------------
extern "C" void kernel_launch(void* const* d_in, const int* in_sizes, int n_in,
                              void* d_out, int out_size)
{
    const float* feats = (const float*)d_in[0];
    const int*   tags  = (const int*)d_in[1];
    const float* Wd    = (const float*)d_in[2];
    const float* bd    = (const float*)d_in[3];
    const float* Wl    = (const float*)d_in[4];
    const float* bl    = (const float*)d_in[5];
    const float* Wr    = (const float*)d_in[6];
    const float* br    = (const float*)d_in[7];
    const float* Gl    = (const float*)d_in[8];
    const float* bgl   = (const float*)d_in[9];
    const float* Gr    = (const float*)d_in[10];
    const float* bgr   = (const float*)d_in[11];
    const float* Wt    = (const float*)d_in[12];
    const float* bt    = (const float*)d_in[13];
    const float* trans = (const float*)d_in[14];
    float* out = (float*)d_out;

    mega_kernel<<<NCTA, 256>>>(feats, Wd, bd, Wl, Wr, Gl, Gr,
                               bl, br, bgl, bgr, Wt, bt, trans, tags, out);
}